// round 6
// baseline (speedup 1.0000x reference)
#include <cuda_runtime.h>
#include <cuda_bf16.h>

// Fixed shapes from reference setup_inputs
#define NPTS 8192
#define TPB  256
#define TILE 512                     // i-tile edge (TPB * 2 packed i per thread)
#define JC   128                     // j-chunk per CTA
#define NTILES (NPTS / TILE)         // 16
#define NTRI (NTILES * (NTILES + 1) / 2)   // 136 triangular tiles
#define NBLK (NTRI * 4)              // 544 CTAs

typedef unsigned long long u64;

__device__ float g_partials[NBLK];
__device__ unsigned int g_count;     // zero at load; self-reset each launch

// A&S 7.1.26, x = r/sqrt(2) folded, coefficients negated
#define P_OVER_SQRT2   0.23170396f
#define NA1c  (-0.254829592f)
#define NA2c  ( 0.284496736f)
#define NA3c  (-1.421413741f)
#define NA4c  ( 1.453152027f)
#define NA5c  (-1.061405429f)
#define NEG_HALF_LOG2E (-0.7213475204444817f)
#define SELF_RATIO 0.7978845608028654f   // (1/(2pi)^1.5) / (1/(4pi))

// ---- packed f32x2 helpers ----
__device__ __forceinline__ u64 ffma2(u64 a, u64 b, u64 c) {
    u64 d; asm("fma.rn.f32x2 %0,%1,%2,%3;" : "=l"(d) : "l"(a), "l"(b), "l"(c)); return d;
}
__device__ __forceinline__ u64 fmul2(u64 a, u64 b) {
    u64 d; asm("mul.rn.f32x2 %0,%1,%2;" : "=l"(d) : "l"(a), "l"(b)); return d;
}
__device__ __forceinline__ u64 fadd2(u64 a, u64 b) {
    u64 d; asm("add.rn.f32x2 %0,%1,%2;" : "=l"(d) : "l"(a), "l"(b)); return d;
}
__device__ __forceinline__ u64 pack2(float lo, float hi) {
    u64 d; asm("mov.b64 %0,{%1,%2};" : "=l"(d) : "f"(lo), "f"(hi)); return d;
}
__device__ __forceinline__ float2 unpack2(u64 v) {
    float2 f; asm("mov.b64 {%0,%1},%2;" : "=f"(f.x), "=f"(f.y) : "l"(v)); return f;
}
// scalar MUFU with float constraints (no mov.b64 inside the asm)
__device__ __forceinline__ float rsqf(float a) {
    float r; asm("rsqrt.approx.f32 %0,%1;" : "=f"(r) : "f"(a)); return r;
}
__device__ __forceinline__ float rcpf(float a) {
    float r; asm("rcp.approx.f32 %0,%1;" : "=f"(r) : "f"(a)); return r;
}
__device__ __forceinline__ float exf(float a) {
    float r; asm("ex2.approx.f32 %0,%1;" : "=f"(r) : "f"(a)); return r;
}
__device__ __forceinline__ u64 rsq2(u64 a) {
    float2 f = unpack2(a); return pack2(rsqf(f.x), rsqf(f.y));
}
__device__ __forceinline__ u64 rcp2(u64 a) {
    float2 f = unpack2(a); return pack2(rcpf(f.x), rcpf(f.y));
}
__device__ __forceinline__ u64 ex22(u64 a) {
    float2 f = unpack2(a); return pack2(exf(f.x), exf(f.y));
}

__global__ void __launch_bounds__(TPB, 4)
ewald_pair_kernel(const float* __restrict__ pos, const float* __restrict__ q,
                  float* __restrict__ out) {
    // j-chunk SoA, lane-duplicated u64s, 4x LDS.128 per row:
    //   v_xy : {x, y}    v_zs : {z, |p|^2}    v_b01: {b0, b1}   v_b23: {b2, b3}
    __shared__ __align__(16) ulonglong2 v_xy [JC];
    __shared__ __align__(16) ulonglong2 v_zs [JC];
    __shared__ __align__(16) ulonglong2 v_b01[JC];
    __shared__ __align__(16) ulonglong2 v_b23[JC];

    const int t = threadIdx.x;

    // block -> (tile, chunk) -> (I, J)
    const int tile  = blockIdx.x >> 2;
    const int chunk = blockIdx.x & 3;
    int I = 0, rem = tile;
    while (rem >= NTILES - I) { rem -= NTILES - I; I++; }
    const int J = I + rem;
    const bool diag = (I == J);

    const int jbase = J * TILE + chunk * JC;
    if (t < JC) {                 // warps 0-3: positions + |p|^2
        const int j = jbase + t;
        const float x = pos[3 * j + 0];
        const float y = pos[3 * j + 1];
        const float z = pos[3 * j + 2];
        const float s = fmaf(x, x, fmaf(y, y, z * z));
        ulonglong2 e;
        e.x = pack2(x, x); e.y = pack2(y, y); v_xy[t] = e;
        e.x = pack2(z, z); e.y = pack2(s, s); v_zs[t] = e;
    } else {                      // warps 4-7: charges
        const int tq = t - JC;
        const int j  = jbase + tq;
        const float b0 = q[4 * j + 0], b1 = q[4 * j + 1];
        const float b2 = q[4 * j + 2], b3 = q[4 * j + 3];
        ulonglong2 e;
        e.x = pack2(b0, b0); e.y = pack2(b1, b1); v_b01[tq] = e;
        e.x = pack2(b2, b2); e.y = pack2(b3, b3); v_b23[tq] = e;
    }
    __syncthreads();

    // i pair for this thread: (i0, i0+1)
    const int i0 = I * TILE + 2 * t;
    const float x0 = pos[3 * i0 + 0], x1 = pos[3 * i0 + 3];
    const float y0 = pos[3 * i0 + 1], y1 = pos[3 * i0 + 4];
    const float z0 = pos[3 * i0 + 2], z1 = pos[3 * i0 + 5];

    // packed constants
    const u64 P2   = pack2(P_OVER_SQRT2, P_OVER_SQRT2);
    const u64 ONE2 = pack2(1.0f, 1.0f);
    const u64 N5   = pack2(NA5c, NA5c), N4 = pack2(NA4c, NA4c);
    const u64 N3   = pack2(NA3c, NA3c), N2 = pack2(NA2c, NA2c);
    const u64 N1   = pack2(NA1c, NA1c);
    const u64 NHL  = pack2(NEG_HALF_LOG2E, NEG_HALF_LOG2E);

    // per-channel packed accumulators (4 independent chains)
    u64 acc0 = 0ull, acc1 = 0ull, acc2 = 0ull, acc3 = 0ull;

    if (!diag) {
        // dot-form r^2: r2 = (si+sj) - 2*pi.pj  (4 FFMA2 incl. the add)
        const u64 nxi2 = pack2(-2.0f * x0, -2.0f * x1);
        const u64 nyi2 = pack2(-2.0f * y0, -2.0f * y1);
        const u64 nzi2 = pack2(-2.0f * z0, -2.0f * z1);
        const u64 si   = pack2(fmaf(x0, x0, fmaf(y0, y0, z0 * z0)),
                               fmaf(x1, x1, fmaf(y1, y1, z1 * z1)));
#pragma unroll 8
        for (int jj = 0; jj < JC; jj++) {
            const ulonglong2 xy = v_xy[jj];
            const ulonglong2 zs = v_zs[jj];
            const u64 sij = fadd2(zs.y, si);
            const u64 r2  = ffma2(xy.x, nxi2,
                            ffma2(xy.y, nyi2,
                            ffma2(zs.x, nzi2, sij)));
            const u64 rinv = rsq2(r2);
            const u64 r  = fmul2(r2, rinv);
            const u64 dd = ffma2(P2, r, ONE2);
            const u64 tt = rcp2(dd);
            u64 pn = ffma2(N5, tt, N4);
            pn = ffma2(pn, tt, N3);
            pn = ffma2(pn, tt, N2);
            pn = ffma2(pn, tt, N1);
            const u64 ex   = ex22(fmul2(r2, NHL));
            const u64 te   = fmul2(tt, ex);
            const u64 erfv = ffma2(pn, te, ONE2);
            const u64 kern = fmul2(erfv, rinv);
            const ulonglong2 b01 = v_b01[jj];
            const ulonglong2 b23 = v_b23[jj];
            acc0 = ffma2(kern, b01.x, acc0);
            acc1 = ffma2(kern, b01.y, acc1);
            acc2 = ffma2(kern, b23.x, acc2);
            acc3 = ffma2(kern, b23.y, acc3);
        }
    } else {
        // exact diff-form r^2 (diagonal must be exactly zero for the select)
        const u64 nxi = pack2(-x0, -x1);
        const u64 nyi = pack2(-y0, -y1);
        const u64 nzi = pack2(-z0, -z1);
#pragma unroll 8
        for (int jj = 0; jj < JC; jj++) {
            const ulonglong2 xy = v_xy[jj];
            const ulonglong2 zs = v_zs[jj];
            const u64 dx = fadd2(xy.x, nxi);
            const u64 dy = fadd2(xy.y, nyi);
            const u64 dz = fadd2(zs.x, nzi);
            const u64 r2 = ffma2(dx, dx, ffma2(dy, dy, fmul2(dz, dz)));
            const u64 rinv = rsq2(r2);
            const u64 r  = fmul2(r2, rinv);
            const u64 dd = ffma2(P2, r, ONE2);
            const u64 tt = rcp2(dd);
            u64 pn = ffma2(N5, tt, N4);
            pn = ffma2(pn, tt, N3);
            pn = ffma2(pn, tt, N2);
            pn = ffma2(pn, tt, N1);
            const u64 ex   = ex22(fmul2(r2, NHL));
            const u64 te   = fmul2(tt, ex);
            const u64 erfv = ffma2(pn, te, ONE2);
            u64 kern = fmul2(erfv, rinv);
            {   // exact-zero diagonal (r2 == 0 -> kern NaN -> select 0)
                float2 kf = unpack2(kern);
                float2 rf = unpack2(r2);
                kf.x = (rf.x > 0.0f) ? kf.x : 0.0f;
                kf.y = (rf.y > 0.0f) ? kf.y : 0.0f;
                kern = pack2(kf.x, kf.y);
            }
            const ulonglong2 b01 = v_b01[jj];
            const ulonglong2 b23 = v_b23[jj];
            acc0 = ffma2(kern, b01.x, acc0);
            acc1 = ffma2(kern, b01.y, acc1);
            acc2 = ffma2(kern, b23.x, acc2);
            acc3 = ffma2(kern, b23.y, acc3);
        }
    }

    // Reload i charges (L1 hit) and dot with per-channel accumulators
    const float a0x = q[4 * i0 + 0], a0y = q[4 * i0 + 4];
    const float a1x = q[4 * i0 + 1], a1y = q[4 * i0 + 5];
    const float a2x = q[4 * i0 + 2], a2y = q[4 * i0 + 6];
    const float a3x = q[4 * i0 + 3], a3y = q[4 * i0 + 7];
    const float2 f0 = unpack2(acc0), f1 = unpack2(acc1);
    const float2 f2 = unpack2(acc2), f3 = unpack2(acc3);
    float s = fmaf(a0x, f0.x, fmaf(a1x, f1.x, fmaf(a2x, f2.x, a3x * f3.x)))
            + fmaf(a0y, f0.y, fmaf(a1y, f1.y, fmaf(a2y, f2.y, a3y * f3.y)));
    if (!diag) s = s + s;
    else if (chunk == 0) {
        const float qq = fmaf(a0x, a0x, fmaf(a1x, a1x, fmaf(a2x, a2x, a3x * a3x)))
                       + fmaf(a0y, a0y, fmaf(a1y, a1y, fmaf(a2y, a2y, a3y * a3y)));
        s = fmaf(SELF_RATIO, qq, s);
    }

    // deterministic in-block reduction (8 warps)
#pragma unroll
    for (int o = 16; o > 0; o >>= 1)
        s += __shfl_down_sync(0xffffffffu, s, o);

    __shared__ float red[TPB / 32];
    if ((t & 31) == 0) red[t >> 5] = s;
    __syncthreads();

    __shared__ bool is_last;
    if (t == 0) {
        g_partials[blockIdx.x] = ((red[0] + red[1]) + (red[2] + red[3]))
                               + ((red[4] + red[5]) + (red[6] + red[7]));
        __threadfence();
        const unsigned int c = atomicAdd(&g_count, 1u);
        is_last = (c == NBLK - 1);
    }
    __syncthreads();

    // last CTA: fixed-order fp64 final reduction + scale
    if (is_last) {
        __threadfence();
        double d = (double)g_partials[t] + (double)g_partials[t + 256];
        if (t < NBLK - 512) d += (double)g_partials[t + 512];

        __shared__ double rs[TPB];
        rs[t] = d;
        __syncthreads();
#pragma unroll
        for (int o = TPB / 2; o > 0; o >>= 1) {
            if (t < o) rs[t] += rs[t + o];
            __syncthreads();
        }
        if (t == 0) {
            const double INV_4PI = 0.07957747154594767;
            out[0] = (float)(rs[0] * INV_4PI);
            g_count = 0;   // reset for next graph replay
        }
    }
}

extern "C" void kernel_launch(void* const* d_in, const int* in_sizes, int n_in,
                              void* d_out, int out_size) {
    const float* pos = (const float*)d_in[0];   // [8192,3] fp32
    const float* q   = (const float*)d_in[1];   // [8192,4] fp32
    float* out = (float*)d_out;                 // [1] fp32

    ewald_pair_kernel<<<NBLK, TPB>>>(pos, q, out);
}